// round 5
// baseline (speedup 1.0000x reference)
#include <cuda_runtime.h>
#include <math.h>
#include <float.h>

// AUAvULoss: N=65536 rows, C=1000 classes fp32 logits, int64 labels.
// Two kernels, NO init kernel, no contended atomics:
//  k_rows: one warp/row -> g_unc,g_confacc + per-block (min,max,ce) partials
//          (plain stores, full overwrite each replay).
//  k_bins: every block redundantly reduces the min/max partials (L2-resident),
//          bins its slice into shared, stores its 88 bins to a private slot;
//          a monotonic done-counter (replay-safe modulo test) elects the last
//          block, which sums partial bins + ce partials and emits the scalar.

#define MAXN 65536
#define WPB 8
#define NROWBLK (MAXN / WPB)     // 8192
#define BINGRID 256

__device__ float g_unc[MAXN];
__device__ float g_confacc[MAXN];        // +conf if accurate, -conf if not
__device__ float g_pmin[NROWBLK];
__device__ float g_pmax[NROWBLK];
__device__ float g_pce[NROWBLK];
__device__ float g_bins_part[BINGRID][88];
__device__ unsigned int g_done;          // monotonic across graph replays

// ---------------- K1: one warp per row, per-block partials ----------------
__global__ void __launch_bounds__(WPB * 32)
k_rows(const float* __restrict__ logits,
       const long long* __restrict__ labels,
       int C, int n) {
    const int wid  = threadIdx.x >> 5;
    const int lane = threadIdx.x & 31;
    const int row  = blockIdx.x * WPB + wid;
    const bool active = (row < n);

    __shared__ float s_unc[WPB];
    __shared__ float s_ce[WPB];

    if (active) {
        const int chunks = (C + 3) >> 2;          // 250 for C=1000
        const float4* __restrict__ rp =
            reinterpret_cast<const float4*>(logits + (size_t)row * (size_t)C);

        // front-batched streaming loads: up to 8 float4 per lane
        float4 v[8];
        bool   ok[8];
        #pragma unroll
        for (int k = 0; k < 8; k++) {
            int c = lane + (k << 5);
            ok[k] = (c < chunks);
            if (ok[k]) v[k] = __ldcs(&rp[c]);
        }

        // local max + first-index argmax
        float m = -FLT_MAX;
        int mi = 0x7FFFFFFF;
        #pragma unroll
        for (int k = 0; k < 8; k++) {
            if (ok[k]) {
                int base = (lane + (k << 5)) << 2;
                if (v[k].x > m) { m = v[k].x; mi = base; }
                if (v[k].y > m) { m = v[k].y; mi = base + 1; }
                if (v[k].z > m) { m = v[k].z; mi = base + 2; }
                if (v[k].w > m) { m = v[k].w; mi = base + 3; }
            }
        }
        #pragma unroll
        for (int o = 16; o > 0; o >>= 1) {
            float om = __shfl_xor_sync(0xffffffffu, m, o);
            int   oi = __shfl_xor_sync(0xffffffffu, mi, o);
            if (om > m || (om == m && oi < mi)) { m = om; mi = oi; }
        }
        const float rm = m;
        const int pred = mi;

        // S = sum e^d, T = sum d*e^d over registers
        float S = 0.0f, T = 0.0f;
        #pragma unroll
        for (int k = 0; k < 8; k++) {
            if (ok[k]) {
                float d, e;
                d = v[k].x - rm; e = __expf(d); S += e; T = fmaf(d, e, T);
                d = v[k].y - rm; e = __expf(d); S += e; T = fmaf(d, e, T);
                d = v[k].z - rm; e = __expf(d); S += e; T = fmaf(d, e, T);
                d = v[k].w - rm; e = __expf(d); S += e; T = fmaf(d, e, T);
            }
        }
        #pragma unroll
        for (int o = 16; o > 0; o >>= 1) {
            S += __shfl_xor_sync(0xffffffffu, S, o);
            T += __shfl_xor_sync(0xffffffffu, T, o);
        }

        if (lane == 0) {
            int lbl = (int)labels[row];
            float zl = __ldg(&logits[(size_t)row * (size_t)C + lbl]); // L1 hit
            float conf = 1.0f / S;
            float logS = logf(S);
            float unc  = logS - T / S;              // entropy
            float ce   = (rm - zl) + logS;          // -log_softmax at label
            g_unc[row]     = unc;
            g_confacc[row] = (pred == lbl) ? conf : -conf;
            s_unc[wid] = unc;
            s_ce[wid]  = ce;
        }
    } else if (lane == 0) {
        s_unc[wid] = 0.0f;
        s_ce[wid]  = 0.0f;
    }
    __syncthreads();

    // per-block (min, max, ce) -> plain stores to private slots
    if (threadIdx.x == 0) {
        int valid = n - blockIdx.x * WPB;
        if (valid > WPB) valid = WPB;
        float mn = FLT_MAX, mx = -FLT_MAX, cs = 0.0f;
        for (int w = 0; w < valid; w++) {
            float u = s_unc[w];
            mn = fminf(mn, u);
            mx = fmaxf(mx, u);
            cs += s_ce[w];
        }
        g_pmin[blockIdx.x] = mn;
        g_pmax[blockIdx.x] = mx;
        g_pce[blockIdx.x]  = cs;
    }
}

// ---------------- K2: minmax-reduce + histogram + fused final ----------------
template <int BLK>
__global__ void __launch_bounds__(BLK)
k_bins(float* __restrict__ out, int n, int nrowblk) {
    __shared__ float sb[88];
    __shared__ float s_mn[BLK / 32], s_mx[BLK / 32];
    __shared__ float s_bcast[2];
    __shared__ bool  is_last;

    const int tid  = threadIdx.x;
    const int lane = tid & 31;
    const int wid  = tid >> 5;

    if (tid < 88) sb[tid] = 0.0f;

    // phase A: every block redundantly reduces the L2-resident partials
    float mn = FLT_MAX, mx = -FLT_MAX;
    for (int i = tid; i < nrowblk; i += BLK) {
        mn = fminf(mn, g_pmin[i]);
        mx = fmaxf(mx, g_pmax[i]);
    }
    #pragma unroll
    for (int o = 16; o > 0; o >>= 1) {
        mn = fminf(mn, __shfl_xor_sync(0xffffffffu, mn, o));
        mx = fmaxf(mx, __shfl_xor_sync(0xffffffffu, mx, o));
    }
    if (lane == 0) { s_mn[wid] = mn; s_mx[wid] = mx; }
    __syncthreads();
    if (tid == 0) {
        for (int w = 1; w < BLK / 32; w++) {
            mn = fminf(mn, s_mn[w]);
            mx = fmaxf(mx, s_mx[w]);
        }
        s_bcast[0] = mn;
        s_bcast[1] = mx;
    }
    __syncthreads();
    const float umin  = s_bcast[0];
    const float range = s_bcast[1] - umin;

    // phase B: bin this block's slice
    for (int i = blockIdx.x * BLK + tid; i < n; i += gridDim.x * BLK) {
        float unc = g_unc[i];
        float ca  = g_confacc[i];
        int acc   = (ca > 0.0f) ? 1 : 0;
        float conf = fabsf(ca);
        float w = acc ? conf : (1.0f - conf);
        // tanh(u), u >= 0:  1 - 2/(e^{2u}+1)
        float t = 1.0f - 2.0f / (__expf(2.0f * unc) + 1.0f);
        float bc = w * (1.0f - t);   // contribution if certain
        float bu = w * t;            // contribution if uncertain
        int j0 = 21;                 // smallest j with unc <= th_j
        #pragma unroll
        for (int j = 20; j >= 0; j--) {
            float thv = umin + (0.05f * (float)j) * range;
            if (unc <= thv) j0 = j;
        }
        atomicAdd(&sb[acc * 44 + j0], bc);
        atomicAdd(&sb[acc * 44 + 22 + j0], bu);
    }
    __syncthreads();
    if (tid < 88) g_bins_part[blockIdx.x][tid] = sb[tid];   // plain store

    // last-block election: monotonic counter, replay-safe modulo test
    __threadfence();
    if (tid == 0) {
        unsigned int d = atomicAdd(&g_done, 1u);
        is_last = (d % gridDim.x == gridDim.x - 1);
    }
    __syncthreads();
    if (!is_last) return;

    // phase C (last block only): reduce partial bins + ce, emit scalar
    __shared__ float fb[88];
    __shared__ float s_cs[BLK / 32];
    if (tid < 88) {
        float s = 0.0f;
        for (int b = 0; b < BINGRID; b++) s += g_bins_part[b][tid];
        fb[tid] = s;
    }
    float cs = 0.0f;
    for (int i = tid; i < nrowblk; i += BLK) cs += g_pce[i];
    #pragma unroll
    for (int o = 16; o > 0; o >>= 1)
        cs += __shfl_xor_sync(0xffffffffu, cs, o);
    if (lane == 0) s_cs[wid] = cs;
    __syncthreads();

    if (tid == 0) {
        float cesum = 0.0f;
        for (int w = 0; w < BLK / 32; w++) cesum += s_cs[w];

        float au_rem = 0.0f, iu_rem = 0.0f;
        for (int k = 0; k < 22; k++) {
            au_rem += fb[66 + k];   // acc=1, kind=U
            iu_rem += fb[22 + k];   // acc=0, kind=U
        }
        float nac = 0.0f, nic = 0.0f;
        float avu[21];
        for (int j = 0; j < 21; j++) {
            nac    += fb[44 + j];   // acc=1, kind=C prefix
            nic    += fb[j];        // acc=0, kind=C prefix
            au_rem -= fb[66 + j];
            iu_rem -= fb[22 + j];
            avu[j] = (nac + iu_rem) / (nac + au_rem + nic + iu_rem + 1e-12f);
        }
        float auc = 0.0f;
        for (int j = 0; j < 20; j++) auc += (avu[j + 1] + avu[j]);
        auc *= 0.5f * 0.05f;
        out[0] = -3.0f * logf(auc + 1e-12f) + cesum / (float)n;
    }
}

extern "C" void kernel_launch(void* const* d_in, const int* in_sizes, int n_in,
                              void* d_out, int out_size) {
    const float*     logits = (const float*)d_in[0];
    const long long* labels = (const long long*)d_in[1];
    int n = in_sizes[1];
    int C = in_sizes[0] / n;
    int nrowblk = (n + WPB - 1) / WPB;

    k_rows<<<nrowblk, WPB * 32>>>(logits, labels, C, n);
    k_bins<256><<<BINGRID, 256>>>((float*)d_out, n, nrowblk);
}

// round 6
// speedup vs baseline: 1.0702x; 1.0702x over previous
#include <cuda_runtime.h>
#include <math.h>
#include <float.h>

// AUAvULoss: N=65536 rows, C=1000 classes fp32 logits, int64 labels.
//  k_rows: one warp/row (R3-exact body) -> g_unc / g_confacc / g_ce
//  k_mm:   64-block parallel reduce -> g_pmin/g_pmax/g_pce[64] (plain stores)
//  k_bins: phase A reduces 64 partials, bins 1 elem/thread, atomicAdd into
//          g_bins; last block (monotonic counter) computes the scalar and
//          re-zeroes g_bins for the next replay (no init kernel needed:
//          __device__ globals start zeroed, every run leaves them zeroed).

#define MAXN 65536
#define MMGRID 64

__device__ float g_unc[MAXN];
__device__ float g_confacc[MAXN];   // +conf if accurate, -conf if not
__device__ float g_ce[MAXN];
__device__ float g_pmin[MMGRID];
__device__ float g_pmax[MMGRID];
__device__ float g_pce[MMGRID];
__device__ float g_bins[88];        // zero at load; last block re-zeroes
__device__ unsigned int g_done;     // monotonic; tested modulo gridDim

// ---------------- K1: one warp per row (R3-exact) ----------------
template <int WPB>
__global__ void __launch_bounds__(WPB * 32)
k_rows(const float* __restrict__ logits,
       const long long* __restrict__ labels,
       int C, int n) {
    const int warp = blockIdx.x * WPB + (threadIdx.x >> 5);
    if (warp >= n) return;
    const int row  = warp;
    const int lane = threadIdx.x & 31;
    const int chunks = (C + 3) >> 2;          // 250 for C=1000
    const float4* __restrict__ rp =
        reinterpret_cast<const float4*>(logits + (size_t)row * (size_t)C);

    float4 v[8];
    bool   ok[8];
    #pragma unroll
    for (int k = 0; k < 8; k++) {
        int c = lane + (k << 5);
        ok[k] = (c < chunks);
        if (ok[k]) v[k] = rp[c];
    }

    float m = -FLT_MAX;
    int mi = 0x7FFFFFFF;
    #pragma unroll
    for (int k = 0; k < 8; k++) {
        if (ok[k]) {
            int base = (lane + (k << 5)) << 2;
            if (v[k].x > m) { m = v[k].x; mi = base; }
            if (v[k].y > m) { m = v[k].y; mi = base + 1; }
            if (v[k].z > m) { m = v[k].z; mi = base + 2; }
            if (v[k].w > m) { m = v[k].w; mi = base + 3; }
        }
    }
    #pragma unroll
    for (int o = 16; o > 0; o >>= 1) {
        float om = __shfl_xor_sync(0xffffffffu, m, o);
        int   oi = __shfl_xor_sync(0xffffffffu, mi, o);
        if (om > m || (om == m && oi < mi)) { m = om; mi = oi; }
    }
    const float rm = m;
    const int pred = mi;

    float S = 0.0f, T = 0.0f;
    #pragma unroll
    for (int k = 0; k < 8; k++) {
        if (ok[k]) {
            float d, e;
            d = v[k].x - rm; e = __expf(d); S += e; T = fmaf(d, e, T);
            d = v[k].y - rm; e = __expf(d); S += e; T = fmaf(d, e, T);
            d = v[k].z - rm; e = __expf(d); S += e; T = fmaf(d, e, T);
            d = v[k].w - rm; e = __expf(d); S += e; T = fmaf(d, e, T);
        }
    }
    #pragma unroll
    for (int o = 16; o > 0; o >>= 1) {
        S += __shfl_xor_sync(0xffffffffu, S, o);
        T += __shfl_xor_sync(0xffffffffu, T, o);
    }

    if (lane == 0) {
        int lbl = (int)labels[row];
        float zl = __ldg(&logits[(size_t)row * (size_t)C + lbl]); // L1 hit
        float conf = 1.0f / S;
        float logS = logf(S);
        float unc  = logS - T / S;              // entropy
        float ce   = (rm - zl) + logS;          // -log_softmax at label
        g_unc[row]     = unc;
        g_confacc[row] = (pred == lbl) ? conf : -conf;
        g_ce[row]      = ce;
    }
}

// ---------------- K2: 64-block minmax + ce partial reduce ----------------
template <int BLK>
__global__ void __launch_bounds__(BLK)
k_mm(int n) {
    const int tid  = threadIdx.x;
    const int lane = tid & 31;
    const int wid  = tid >> 5;
    float mn = FLT_MAX, mx = -FLT_MAX, cs = 0.0f;
    for (int i = blockIdx.x * BLK + tid; i < n; i += MMGRID * BLK) {
        float u = g_unc[i];
        mn = fminf(mn, u);
        mx = fmaxf(mx, u);
        cs += g_ce[i];
    }
    #pragma unroll
    for (int o = 16; o > 0; o >>= 1) {
        mn = fminf(mn, __shfl_xor_sync(0xffffffffu, mn, o));
        mx = fmaxf(mx, __shfl_xor_sync(0xffffffffu, mx, o));
        cs += __shfl_xor_sync(0xffffffffu, cs, o);
    }
    __shared__ float sm[BLK / 32], sx[BLK / 32], sc[BLK / 32];
    if (lane == 0) { sm[wid] = mn; sx[wid] = mx; sc[wid] = cs; }
    __syncthreads();
    if (tid == 0) {
        for (int w = 1; w < BLK / 32; w++) {
            mn = fminf(mn, sm[w]);
            mx = fmaxf(mx, sx[w]);
            cs += sc[w];
        }
        g_pmin[blockIdx.x] = mn;
        g_pmax[blockIdx.x] = mx;
        g_pce[blockIdx.x]  = cs;
    }
}

// ---------------- K3: histogram + fused final scalar ----------------
template <int BLK>
__global__ void __launch_bounds__(BLK)
k_bins(float* __restrict__ out, int n) {
    __shared__ float sb[88];
    __shared__ float s_red[BLK / 32];
    __shared__ float s_bcast[2];
    __shared__ bool  is_last;

    const int tid  = threadIdx.x;
    const int lane = tid & 31;
    const int wid  = tid >> 5;

    if (tid < 88) sb[tid] = 0.0f;

    // phase A: reduce the 64 partials (2 loads for tid<64)
    float mn = (tid < MMGRID) ? g_pmin[tid] : FLT_MAX;
    float mx = (tid < MMGRID) ? g_pmax[tid] : -FLT_MAX;
    #pragma unroll
    for (int o = 16; o > 0; o >>= 1) {
        mn = fminf(mn, __shfl_xor_sync(0xffffffffu, mn, o));
        mx = fmaxf(mx, __shfl_xor_sync(0xffffffffu, mx, o));
    }
    if (lane == 0) { s_red[wid] = mn; s_red[wid + BLK / 32] = mx; }  // see below
    __syncthreads();
    if (tid == 0) {
        float a = fminf(s_red[0], s_red[1]);            // warps 0,1 cover tid<64
        float b = fmaxf(s_red[BLK / 32], s_red[BLK / 32 + 1]);
        s_bcast[0] = a;
        s_bcast[1] = b;
    }
    __syncthreads();
    const float umin  = s_bcast[0];
    const float range = s_bcast[1] - umin;

    // phase B: one element per thread
    const int i = blockIdx.x * BLK + tid;
    if (i < n) {
        float unc = g_unc[i];
        float ca  = g_confacc[i];
        int acc   = (ca > 0.0f) ? 1 : 0;
        float conf = fabsf(ca);
        float w = acc ? conf : (1.0f - conf);
        // tanh(u), u >= 0:  1 - 2/(e^{2u}+1)
        float t = 1.0f - 2.0f / (__expf(2.0f * unc) + 1.0f);
        float bc = w * (1.0f - t);
        float bu = w * t;
        int j0 = 21;
        #pragma unroll
        for (int j = 20; j >= 0; j--) {
            float thv = umin + (0.05f * (float)j) * range;
            if (unc <= thv) j0 = j;
        }
        atomicAdd(&sb[acc * 44 + j0], bc);
        atomicAdd(&sb[acc * 44 + 22 + j0], bu);
    }
    __syncthreads();
    if (tid < 88) {
        float v = sb[tid];
        if (v != 0.0f) atomicAdd(&g_bins[tid], v);   // 88 spread addresses
    }

    // last-block election (monotonic counter; 2^32 % gridDim == 0 safe for 256)
    __threadfence();
    if (tid == 0) {
        unsigned int d = atomicAdd(&g_done, 1u);
        is_last = (d % gridDim.x == gridDim.x - 1);
    }
    __syncthreads();
    if (!is_last) return;

    // phase C: read + re-zero bins, reduce ce partials, emit scalar
    __shared__ float fb[88];
    __shared__ float s_cs;
    if (tid < 88) {
        fb[tid] = g_bins[tid];
        g_bins[tid] = 0.0f;                  // leave zeroed for next replay
    }
    if (tid == 0) {
        float cs = 0.0f;
        for (int b = 0; b < MMGRID; b++) cs += g_pce[b];
        s_cs = cs;
    }
    __syncthreads();

    if (tid == 0) {
        float au_rem = 0.0f, iu_rem = 0.0f;
        for (int k = 0; k < 22; k++) {
            au_rem += fb[66 + k];   // acc=1, kind=U
            iu_rem += fb[22 + k];   // acc=0, kind=U
        }
        float nac = 0.0f, nic = 0.0f;
        float avu[21];
        for (int j = 0; j < 21; j++) {
            nac    += fb[44 + j];   // acc=1, kind=C prefix
            nic    += fb[j];        // acc=0, kind=C prefix
            au_rem -= fb[66 + j];
            iu_rem -= fb[22 + j];
            avu[j] = (nac + iu_rem) / (nac + au_rem + nic + iu_rem + 1e-12f);
        }
        float auc = 0.0f;
        for (int j = 0; j < 20; j++) auc += (avu[j + 1] + avu[j]);
        auc *= 0.5f * 0.05f;
        out[0] = -3.0f * logf(auc + 1e-12f) + s_cs / (float)n;
    }
}

extern "C" void kernel_launch(void* const* d_in, const int* in_sizes, int n_in,
                              void* d_out, int out_size) {
    const float*     logits = (const float*)d_in[0];
    const long long* labels = (const long long*)d_in[1];
    int n = in_sizes[1];
    int C = in_sizes[0] / n;

    const int WPB = 8;
    k_rows<WPB><<<(n + WPB - 1) / WPB, WPB * 32>>>(logits, labels, C, n);
    k_mm<256><<<MMGRID, 256>>>(n);
    k_bins<256><<<(n + 255) / 256, 256>>>((float*)d_out, n);
}